// round 7
// baseline (speedup 1.0000x reference)
#include <cuda_runtime.h>
#include <cstdint>
#include <cstddef>

// Problem dimensions (fixed by the dataset; grid sizes derived from in_sizes)
#define HDIM 64
#define SDIM 256
#define ADIM 18
#define MAXB 1024
#define MAXN 200000

// ---------------- scratch (device globals: allocation-free) ----------------
__device__ float g_scores[(size_t)MAXB * MAXN];   // ~800 MB score matrix
__device__ float g_h[MAXB * HDIM];
__device__ float g_hsq[MAXB];
__device__ float g_ksq[MAXN];

// ---------------- Kernel 1: MLP (h, policy, hsq) ----------------
__global__ void __launch_bounds__(SDIM) mlp_kernel(
    const float* __restrict__ x, const float* __restrict__ W1,
    const float* __restrict__ b1, const float* __restrict__ Wp,
    const float* __restrict__ bp, float* __restrict__ out, int B)
{
    __shared__ float xs[SDIM];
    __shared__ float hs[HDIM];
    __shared__ float ps[4][HDIM];
    int row = blockIdx.x;
    int t = threadIdx.x;

    xs[t] = x[(size_t)row * SDIM + t];
    __syncthreads();

    int j = t & 63;
    int part = t >> 6;               // 4 k-partitions of 64
    const float* w = W1 + (size_t)(part * 64) * HDIM + j;
    const float* xp = xs + part * 64;
    float acc = 0.f;
#pragma unroll 8
    for (int k = 0; k < 64; k++) acc = fmaf(xp[k], w[(size_t)k * HDIM], acc);
    ps[part][j] = acc;
    __syncthreads();

    if (t < HDIM) {
        float h = ps[0][t] + ps[1][t] + ps[2][t] + ps[3][t] + b1[t];
        h = fmaxf(h, 0.f);
        hs[t] = h;
        g_h[row * HDIM + t] = h;
        // h region of output: after policy [B,A] and value [B,1]
        out[(size_t)B * (ADIM + 1) + (size_t)row * HDIM + t] = h;
        ps[0][t] = h * h;
    }
    __syncthreads();

    if (t == 0) {
        float s = 0.f;
        for (int i = 0; i < HDIM; i++) s += ps[0][i];
        g_hsq[row] = s;
    }
    if (t < ADIM) {
        float p = bp[t];
#pragma unroll
        for (int jj = 0; jj < HDIM; jj++) p = fmaf(hs[jj], Wp[jj * ADIM + t], p);
        out[(size_t)row * ADIM + t] = p;
    }
}

// ---------------- Kernel 2: key squared norms ----------------
__global__ void ksq_kernel(const float* __restrict__ Kmem, int N)
{
    int n = blockIdx.x * 256 + threadIdx.x;
    if (n < N) {
        const float4* kr = reinterpret_cast<const float4*>(Kmem + (size_t)n * HDIM);
        float s = 0.f;
#pragma unroll
        for (int i = 0; i < HDIM / 4; i++) {
            float4 v = kr[i];
            s = fmaf(v.x, v.x, s); s = fmaf(v.y, v.y, s);
            s = fmaf(v.z, v.z, s); s = fmaf(v.w, v.w, s);
        }
        g_ksq[n] = s;
    }
}

// ---------------- Kernel 3: fp32 score GEMM ----------------
// score[b][n] = h_b . k_n - 0.5*||k_n||^2   (argmax score == argmin distance)
#define TBm 64     // query rows per block
#define TNn 128    // keys per block
#define HPp 68     // Hst pitch (floats), 16B aligned, padded
#define KPp 132    // Kst pitch (floats), 16B aligned, padded
#define GEMM_SMEM ((HDIM * HPp + HDIM * KPp) * 4)

__global__ void __launch_bounds__(256) gemm_kernel(
    const float* __restrict__ Kmem, int B, int N)
{
    extern __shared__ float sm[];
    float* Hst = sm;                  // [HDIM][HPp] k-major
    float* Kst = sm + HDIM * HPp;     // [HDIM][KPp] k-major
    int tid = threadIdx.x;
    int nBase = blockIdx.x * TNn;
    int rowBase = blockIdx.y * TBm;

    // load H tile (64x64), transposed to k-major
    for (int e = tid; e < TBm * HDIM; e += 256) {
        int r = e >> 6, c = e & 63;
        Hst[c * HPp + r] = g_h[(rowBase + r) * HDIM + c];
    }
    // load K tile (128x64), transposed to k-major, zero-pad past N
    for (int e = tid; e < TNn * HDIM; e += 256) {
        int n = e >> 6, c = e & 63;
        int gn = nBase + n;
        Kst[c * KPp + n] = (gn < N) ? Kmem[(size_t)gn * HDIM + c] : 0.f;
    }
    __syncthreads();

    int tx = tid & 15, ty = tid >> 4;    // 16 x 16 thread grid
    int r0 = tx * 4, n0 = ty * 8;        // 4x8 register tile

    float acc[4][8];
#pragma unroll
    for (int i = 0; i < 4; i++)
#pragma unroll
        for (int jj = 0; jj < 8; jj++) acc[i][jj] = 0.f;

#pragma unroll 16
    for (int kk = 0; kk < HDIM; kk++) {
        float4 a = *reinterpret_cast<const float4*>(Hst + kk * HPp + r0);
        float4 p = *reinterpret_cast<const float4*>(Kst + kk * KPp + n0);
        float4 q = *reinterpret_cast<const float4*>(Kst + kk * KPp + n0 + 4);
        float av[4] = {a.x, a.y, a.z, a.w};
        float bv[8] = {p.x, p.y, p.z, p.w, q.x, q.y, q.z, q.w};
#pragma unroll
        for (int i = 0; i < 4; i++)
#pragma unroll
            for (int jj = 0; jj < 8; jj++)
                acc[i][jj] = fmaf(av[i], bv[jj], acc[i][jj]);
    }

    int gn0 = nBase + n0;
    float kq[8];
#pragma unroll
    for (int jj = 0; jj < 8; jj++) {
        int gn = gn0 + jj;
        kq[jj] = (gn < N) ? 0.5f * g_ksq[gn] : 0.f;
    }
    bool vecok = ((N & 3) == 0) && (gn0 + 8 <= N);
#pragma unroll
    for (int i = 0; i < 4; i++) {
        size_t off = (size_t)(rowBase + r0 + i) * N + gn0;
        if (vecok) {
            float4 o0, o1;
            o0.x = acc[i][0] - kq[0]; o0.y = acc[i][1] - kq[1];
            o0.z = acc[i][2] - kq[2]; o0.w = acc[i][3] - kq[3];
            o1.x = acc[i][4] - kq[4]; o1.y = acc[i][5] - kq[5];
            o1.z = acc[i][6] - kq[6]; o1.w = acc[i][7] - kq[7];
            *reinterpret_cast<float4*>(g_scores + off) = o0;
            *reinterpret_cast<float4*>(g_scores + off + 4) = o1;
        } else {
            for (int jj = 0; jj < 8; jj++)
                if (gn0 + jj < N) g_scores[off + jj] = acc[i][jj] - kq[jj];
        }
    }
}

// ---------------- Kernel 4: streaming top-50 + inverse-distance value ----------------
#define POOL 4096
#define NTSEL 512
#define BATCH 2048
#define KNB 50

__device__ __forceinline__ void bitonic_desc(float* s, int* id, int tid)
{
    for (int k = 2; k <= POOL; k <<= 1) {
        for (int j = k >> 1; j > 0; j >>= 1) {
            for (int i = tid; i < POOL; i += NTSEL) {
                int ixj = i ^ j;
                if (ixj > i) {
                    float a = s[i], b = s[ixj];
                    bool up = ((i & k) == 0);   // descending overall
                    if (up ? (a < b) : (a > b)) {
                        s[i] = b; s[ixj] = a;
                        int t = id[i]; id[i] = id[ixj]; id[ixj] = t;
                    }
                }
            }
            __syncthreads();
        }
    }
}

__global__ void __launch_bounds__(NTSEL) select_kernel(
    const float* __restrict__ vals, float* __restrict__ outv, int B, int N)
{
    __shared__ float cs[POOL];
    __shared__ int   ci[POOL];
    __shared__ int   cnt;
    __shared__ float thr;
    __shared__ float wbuf[KNB], wvbuf[KNB];

    int row = blockIdx.x;
    int tid = threadIdx.x;
    int lane = tid & 31;
    const float* Srow = g_scores + (size_t)row * N;

    if (tid == 0) { cnt = 0; thr = -3.4e38f; }
    __syncthreads();

    for (int base = 0; base < N; base += BATCH) {
        float tloc = thr;
#pragma unroll
        for (int k = 0; k < BATCH / NTSEL; k++) {
            int i = base + k * NTSEL + tid;
            float s = (i < N) ? Srow[i] : -3.4e38f;
            bool pred = (s > tloc);
            unsigned mask = __ballot_sync(0xffffffffu, pred);
            if (mask) {
                int nw = __popc(mask);
                int leader = __ffs(mask) - 1;
                int basep = 0;
                if (lane == leader) basep = atomicAdd(&cnt, nw);
                basep = __shfl_sync(0xffffffffu, basep, leader);
                if (pred) {
                    int p = basep + __popc(mask & ((1u << lane) - 1u));
                    if (p < POOL) { cs[p] = s; ci[p] = i; }
                }
            }
        }
        __syncthreads();
        int c = cnt;                          // uniform after barrier
        if (c >= POOL - BATCH) {              // compact: keep exact top-50 so far
            int cc = c > POOL ? POOL : c;
            for (int i = cc + tid; i < POOL; i += NTSEL) cs[i] = -3.4e38f;
            __syncthreads();
            bitonic_desc(cs, ci, tid);
            if (tid == 0) { thr = cs[KNB - 1]; cnt = KNB; }
            __syncthreads();
        }
    }

    // final exact selection
    int c = cnt;
    int cc = c > POOL ? POOL : c;
    for (int i = cc + tid; i < POOL; i += NTSEL) cs[i] = -3.4e38f;
    __syncthreads();
    bitonic_desc(cs, ci, tid);

    if (tid < KNB) {
        float s = cs[tid];
        float d = fmaxf(g_hsq[row] - 2.0f * s, 0.0f);   // d = hsq - 2(h.k) + ksq, clamped
        float w = 1.0f / (d + 1e-3f);
        wbuf[tid]  = w;
        wvbuf[tid] = w * vals[ci[tid]];
    }
    __syncthreads();
    if (tid == 0) {
        float ws = 0.f, wv = 0.f;
        for (int i = 0; i < KNB; i++) { ws += wbuf[i]; wv += wvbuf[i]; }
        outv[row] = wv / ws;
    }
}

// ---------------- launch ----------------
extern "C" void kernel_launch(void* const* d_in, const int* in_sizes, int n_in,
                              void* d_out, int out_size)
{
    const float* x    = (const float*)d_in[0];
    const float* W1   = (const float*)d_in[1];
    const float* b1   = (const float*)d_in[2];
    const float* Wp   = (const float*)d_in[3];
    const float* bp   = (const float*)d_in[4];
    const float* keys = (const float*)d_in[5];
    const float* vals = (const float*)d_in[6];
    float* out = (float*)d_out;

    int H = in_sizes[2];              // 64
    int S = in_sizes[1] / H;          // 256
    int B = in_sizes[0] / S;          // 1024
    int N = in_sizes[5] / H;          // 200000

    cudaFuncSetAttribute(gemm_kernel,
                         cudaFuncAttributeMaxDynamicSharedMemorySize, GEMM_SMEM);

    mlp_kernel<<<B, SDIM>>>(x, W1, b1, Wp, bp, out, B);
    ksq_kernel<<<(N + 255) / 256, 256>>>(keys, N);
    dim3 g2((N + TNn - 1) / TNn, B / TBm);
    gemm_kernel<<<g2, 256, GEMM_SMEM>>>(keys, B, N);
    // output layout: policy [B,A] | value [B,1] | h [B,H]
    select_kernel<<<B, NTSEL>>>(vals, out + (size_t)B * ADIM, B, N);
}